// round 14
// baseline (speedup 1.0000x reference)
#include <cuda_runtime.h>

// ---------------- problem constants ----------------
#define B_    2
#define C_    64
#define H_    512
#define W_    512
#define T_    16
#define K_    1024
#define KMAX_ 256
#define HID_  128
#define HW_   (H_*W_)
#define CHW_  (C_*HW_)

// output layout (flatten-concat, all f32)
#define HEAVY_OFF  0
#define DET_OFF    33554432
#define ALPHA_OFF  67108864
#define P_OFF      67633152
#define G_OFF      67635200
#define COST_OFF   67637248
#define BL_OFF     67637249

typedef unsigned int u32;
typedef unsigned long long u64;

__device__ int g_sel[B_*K_];
__device__ u32 g_W1hi[4096], g_W1lo[4096];   // [c=64][d-pair=64]  bf16x2
__device__ u32 g_W2hi[4096], g_W2lo[4096];   // [d=128][c-pair=32] bf16x2

// ---------------- helpers ----------------
__device__ __forceinline__ u32 smem_u32(const void* p) {
    u32 a;
    asm("{ .reg .u64 t; cvta.to.shared.u64 t, %1; cvt.u32.u64 %0, t; }"
        : "=r"(a) : "l"(p));
    return a;
}
__device__ __forceinline__ float fast_sigmoid(float v) {
    return __fdividef(1.f, 1.f + __expf(-v));
}
__device__ __forceinline__ float gelu_tanh(float v) {
    float z  = 0.7978845608028654f * fmaf(0.044715f * v, v * v, v);
    float th; asm("tanh.approx.f32 %0, %1;" : "=f"(th) : "f"(z));
    return 0.5f * v * (1.f + th);
}
// split (v0,v1) into packed bf16x2 hi and lo (v ~= hi + lo)
__device__ __forceinline__ void split2(float v0, float v1, u32& hi, u32& lo) {
    u32 h; asm("cvt.rn.bf16x2.f32 %0, %1, %2;" : "=r"(h) : "f"(v1), "f"(v0));
    float f0 = __uint_as_float(h << 16);
    float f1 = __uint_as_float(h & 0xFFFF0000u);
    u32 l; asm("cvt.rn.bf16x2.f32 %0, %1, %2;" : "=r"(l) : "f"(v1 - f1), "f"(v0 - f0));
    hi = h; lo = l;
}
__device__ __forceinline__ float bf_lo(u32 v) { return __uint_as_float(v << 16); }
__device__ __forceinline__ float bf_hi(u32 v) { return __uint_as_float(v & 0xFFFF0000u); }

__device__ __forceinline__ void ldsm4(u32* r, u32 a) {
    asm volatile("ldmatrix.sync.aligned.m8n8.x4.shared.b16 {%0,%1,%2,%3}, [%4];"
        : "=r"(r[0]), "=r"(r[1]), "=r"(r[2]), "=r"(r[3]) : "r"(a));
}
__device__ __forceinline__ void ldsm4t(u32* r, u32 a) {
    asm volatile("ldmatrix.sync.aligned.m8n8.x4.trans.shared.b16 {%0,%1,%2,%3}, [%4];"
        : "=r"(r[0]), "=r"(r[1]), "=r"(r[2]), "=r"(r[3]) : "r"(a));
}
__device__ __forceinline__ void mma16816(float* d, const u32* a, u32 b0, u32 b1) {
    asm volatile(
        "mma.sync.aligned.m16n8k16.row.col.f32.bf16.bf16.f32 "
        "{%0,%1,%2,%3}, {%4,%5,%6,%7}, {%8,%9}, {%0,%1,%2,%3};"
        : "+f"(d[0]), "+f"(d[1]), "+f"(d[2]), "+f"(d[3])
        : "r"(a[0]), "r"(a[1]), "r"(a[2]), "r"(a[3]), "r"(b0), "r"(b1));
}

// ---------------- prep kernel: 5 blocks x 1024 threads ----------------
// blk 0,1: selection (1 thread per element); 2: gate/cost; 3: W1; 4: W2
__global__ void __launch_bounds__(1024)
prep_kernel(const float* __restrict__ u, const float* __restrict__ W1,
            const float* __restrict__ W2, float* __restrict__ out) {
    __shared__ float sh[1024];
    const int blk = blockIdx.x;
    const int t   = threadIdx.x;

    if (blk < 2) {
        // ---- selection: rank-count top-KMAX, one thread per element ----
        float ue = u[blk*K_ + t];
        sh[t] = ue;
        __syncthreads();
        int cnt = 0;
        if (ue >= 0.f) {
            #pragma unroll 8
            for (int j = 0; j < K_; ++j) {
                float uj = sh[j];
                if (uj >= 0.f && (uj > ue || (uj == ue && j < t))) cnt++;
            }
        }
        g_sel[blk*K_ + t] = (ue >= 0.f && cnt < KMAX_) ? 1 : 0;
    } else if (blk == 2) {
        // ---- gate probabilities + cost ----
        float partial = 0.f;
        #pragma unroll
        for (int e = t; e < B_*K_; e += 1024) {
            float uv = u[e];
            float p  = fast_sigmoid(uv);
            float hard = (uv >= 0.f) ? 1.f : 0.f;
            float gate = (hard + p) - p;
            out[P_OFF + e] = p;
            out[G_OFF + e] = gate;
            partial += fmaf(p, 0.9f, 0.1f);
        }
        #pragma unroll
        for (int s = 16; s > 0; s >>= 1)
            partial += __shfl_xor_sync(0xFFFFFFFFu, partial, s);
        if ((t & 31) == 0) sh[t >> 5] = partial;
        __syncthreads();
        if (t < 32) {
            float v = sh[t];
            #pragma unroll
            for (int s = 16; s > 0; s >>= 1)
                v += __shfl_xor_sync(0xFFFFFFFFu, v, s);
            if (t == 0) {
                out[COST_OFF] = v;
                float bl = v - 1024.f;     // BUDGET_TOTAL*B
                out[BL_OFF] = bl > 0.f ? bl : 0.f;
            }
        }
    } else if (blk == 3) {
        // W1 [c=64][d=128] -> bf16 hi/lo, d-pairs packed
        #pragma unroll
        for (int i = t; i < 4096; i += 1024) {
            float2 v = *(const float2*)(W1 + 2*i);
            split2(v.x, v.y, g_W1hi[i], g_W1lo[i]);
        }
    } else {
        // W2 [d=128][c=64] -> bf16 hi/lo, c-pairs packed
        #pragma unroll
        for (int i = t; i < 4096; i += 1024) {
            float2 v = *(const float2*)(W2 + 2*i);
            split2(v.x, v.y, g_W2hi[i], g_W2lo[i]);
        }
    }
}

// ---------------- SMEM layout (byte offsets) ----------------
#define XHI_   0        // [128px][64c] bf16, pitch 144   -> 18432
#define XLO_   18432
#define W1HI_  36864    // [64c][128d] bf16, pitch 272    -> 17408
#define W1LO_  54272
#define W2HI_  71680    // [128d][64c] bf16, pitch 144    -> 18432
#define W2LO_  90112
#define ALPS_  108544   // 128 f32
#define B1S_   109056   // 128 f32
#define B2S_   109568   // 64 f32
#define WAS_   109824   // 64 f32
#define BAS_   110080
#define SMEM_BYTES 110096

// ---------------- main kernel (combined copy + heavy HMMA) ----------------
// grid = 2*B*K half-tile blocks (128 px), 256 threads, 2 CTAs/SM.
__global__ void __launch_bounds__(256, 2)
main_kernel(const float* __restrict__ x,  const float* __restrict__ b1,
            const float* __restrict__ b2, const float* __restrict__ Wa,
            const float* __restrict__ ba, float* __restrict__ out) {
    extern __shared__ char smc[];
    const int blk  = blockIdx.x;
    const int tile = blk >> 1;
    const int half = blk & 1;
    const int b    = tile >> 10;
    const int k    = tile & (K_-1);
    const int gh   = k >> 5, gw = k & 31;
    const int t    = threadIdx.x;

    const int tile_base = b*CHW_ + (gh*T_)*W_ + gw*T_;
    const int rbase = half*8;
    float* heavy = out + HEAVY_OFF;
    float* det   = out + DET_OFF;
    float* alp   = out + ALPHA_OFF;

    if (!g_sel[tile]) {
        // ---- cheap path: heavy = x, detail = 0, alpha = 0 ----
        #pragma unroll 8
        for (int i = t; i < 2048; i += 256) {
            int c = i >> 5; int l = i & 31;
            int off = tile_base + c*HW_ + (rbase + (l >> 2))*W_ + (l & 3)*4;
            float4 v = *(const float4*)(x + off);
            *(float4*)(heavy + off) = v;
            *(float4*)(det   + off) = make_float4(0.f,0.f,0.f,0.f);
        }
        if (t < 32) {
            int aoff = b*HW_ + (gh*T_ + rbase + (t >> 2))*W_ + gw*T_ + (t & 3)*4;
            *(float4*)(alp + aoff) = make_float4(0.f,0.f,0.f,0.f);
        }
        return;
    }

    // ================= staging =================
    #pragma unroll
    for (int it = 0; it < 4; ++it) {
        int s  = it*256 + t;
        int px = s & 127;
        int c8 = s >> 7;
        int gb = tile_base + (rbase + (px >> 4))*W_ + (px & 15);
        float v[8];
        #pragma unroll
        for (int m = 0; m < 8; ++m) v[m] = x[gb + (c8*8 + m)*HW_];
        u32 h[4], l[4];
        split2(v[0], v[1], h[0], l[0]);
        split2(v[2], v[3], h[1], l[1]);
        split2(v[4], v[5], h[2], l[2]);
        split2(v[6], v[7], h[3], l[3]);
        *(uint4*)(smc + XHI_ + px*144 + c8*16) = make_uint4(h[0],h[1],h[2],h[3]);
        *(uint4*)(smc + XLO_ + px*144 + c8*16) = make_uint4(l[0],l[1],l[2],l[3]);
    }
    #pragma unroll
    for (int j = t; j < 2048; j += 256) {
        int c = j >> 5, q = j & 31;
        *(u64*)(smc + W1HI_ + c*272 + q*8) = ((const u64*)g_W1hi)[j];
        *(u64*)(smc + W1LO_ + c*272 + q*8) = ((const u64*)g_W1lo)[j];
    }
    #pragma unroll
    for (int j = t; j < 2048; j += 256) {
        int d = j >> 4, q = j & 15;
        *(u64*)(smc + W2HI_ + d*144 + q*8) = ((const u64*)g_W2hi)[j];
        *(u64*)(smc + W2LO_ + d*144 + q*8) = ((const u64*)g_W2lo)[j];
    }
    if (t < HID_) *(float*)(smc + B1S_ + t*4) = b1[t];
    if (t < C_)  { *(float*)(smc + B2S_ + t*4) = b2[t];
                   *(float*)(smc + WAS_ + t*4) = Wa[t]; }
    if (t == 0)   *(float*)(smc + BAS_) = ba[0];
    __syncthreads();

    const u32 sb   = smem_u32(smc);
    const int wid  = t >> 5, lane = t & 31;
    const int px0  = 16*wid;
    const float* b1s = (const float*)(smc + B1S_);
    const float* b2s = (const float*)(smc + B2S_);
    float* alps = (float*)(smc + ALPS_);

    // ---- alpha: lanes 0-15 each handle one of this warp's 16 px ----
    if (lane < 16) {
        int px = px0 + lane;
        float acc = *(const float*)(smc + BAS_);
        const float* was = (const float*)(smc + WAS_);
        #pragma unroll 8
        for (int c2 = 0; c2 < 32; ++c2) {
            u32 hv = *(const u32*)(smc + XHI_ + px*144 + c2*4);
            u32 lv = *(const u32*)(smc + XLO_ + px*144 + c2*4);
            acc = fmaf(bf_lo(hv) + bf_lo(lv), was[2*c2],   acc);
            acc = fmaf(bf_hi(hv) + bf_hi(lv), was[2*c2+1], acc);
        }
        float av = fast_sigmoid(acc);
        alps[px] = av;
        int aoff = b*HW_ + (gh*T_ + rbase + (px >> 4))*W_ + gw*T_ + (px & 15);
        alp[aoff] = av;
    }
    __syncwarp();

    // ---- fragment base addresses ----
    const u32 lrow16 = (u32)(lane & 15);
    const u32 lhalf  = (u32)(lane >> 4);
    const u32 xA  = sb + XHI_  + (px0 + lrow16)*144 + lhalf*16;
    const u32 xAl = sb + XLO_  + (px0 + lrow16)*144 + lhalf*16;
    const u32 w1A = sb + W1HI_ + lrow16*272 + lhalf*16;
    const u32 w1Al= sb + W1LO_ + lrow16*272 + lhalf*16;
    const u32 w2A = sb + W2HI_ + lrow16*144 + lhalf*16;
    const u32 w2Al= sb + W2LO_ + lrow16*144 + lhalf*16;

    u32 xh[4][4], xl[4][4];
    #pragma unroll
    for (int kt = 0; kt < 4; ++kt) {
        ldsm4(xh[kt], xA  + kt*32);
        ldsm4(xl[kt], xAl + kt*32);
    }

    // ---- GEMM1: D1[16px][128d] ----
    float acc[16][4];
    #pragma unroll
    for (int j = 0; j < 16; ++j)
        #pragma unroll
        for (int q = 0; q < 4; ++q) acc[j][q] = 0.f;

    #pragma unroll
    for (int nt = 0; nt < 8; ++nt) {
        #pragma unroll
        for (int kt = 0; kt < 4; ++kt) {
            u32 bh[4], bl_[4];
            ldsm4t(bh,  w1A  + kt*16*272 + nt*32);
            ldsm4t(bl_, w1Al + kt*16*272 + nt*32);
            mma16816(acc[2*nt],   xh[kt], bh[0],  bh[1]);
            mma16816(acc[2*nt],   xh[kt], bl_[0], bl_[1]);
            mma16816(acc[2*nt],   xl[kt], bh[0],  bh[1]);
            mma16816(acc[2*nt+1], xh[kt], bh[2],  bh[3]);
            mma16816(acc[2*nt+1], xh[kt], bl_[2], bl_[3]);
            mma16816(acc[2*nt+1], xl[kt], bh[2],  bh[3]);
        }
    }

    // ---- D1 -> gelu -> H A-fragments in registers ----
    const int t2 = (lane & 3)*2;
    u32 ah[8][4], al[8][4];
    #pragma unroll
    for (int kt = 0; kt < 8; ++kt) {
        int dbase = 16*kt + t2;
        float bA0 = b1s[dbase],     bA1 = b1s[dbase+1];
        float bB0 = b1s[dbase+8],   bB1 = b1s[dbase+9];
        float h00 = gelu_tanh(acc[2*kt][0]   + bA0);
        float h01 = gelu_tanh(acc[2*kt][1]   + bA1);
        float h10 = gelu_tanh(acc[2*kt][2]   + bA0);
        float h11 = gelu_tanh(acc[2*kt][3]   + bA1);
        float h20 = gelu_tanh(acc[2*kt+1][0] + bB0);
        float h21 = gelu_tanh(acc[2*kt+1][1] + bB1);
        float h30 = gelu_tanh(acc[2*kt+1][2] + bB0);
        float h31 = gelu_tanh(acc[2*kt+1][3] + bB1);
        split2(h00, h01, ah[kt][0], al[kt][0]);
        split2(h10, h11, ah[kt][1], al[kt][1]);
        split2(h20, h21, ah[kt][2], al[kt][2]);
        split2(h30, h31, ah[kt][3], al[kt][3]);
    }

    // ---- GEMM2: D2[16px][64c] ----
    float acc2[8][4];
    #pragma unroll
    for (int j = 0; j < 8; ++j)
        #pragma unroll
        for (int q = 0; q < 4; ++q) acc2[j][q] = 0.f;

    #pragma unroll
    for (int nt = 0; nt < 4; ++nt) {
        #pragma unroll
        for (int kt = 0; kt < 8; ++kt) {
            u32 bh[4], bl_[4];
            ldsm4t(bh,  w2A  + kt*16*144 + nt*32);
            ldsm4t(bl_, w2Al + kt*16*144 + nt*32);
            mma16816(acc2[2*nt],   ah[kt], bh[0],  bh[1]);
            mma16816(acc2[2*nt],   ah[kt], bl_[0], bl_[1]);
            mma16816(acc2[2*nt],   al[kt], bh[0],  bh[1]);
            mma16816(acc2[2*nt+1], ah[kt], bh[2],  bh[3]);
            mma16816(acc2[2*nt+1], ah[kt], bl_[2], bl_[3]);
            mma16816(acc2[2*nt+1], al[kt], bh[2],  bh[3]);
        }
    }

    // ---- epilogue: det = D2 + b2 ; heavy = x + alpha*det ----
    {
        int g   = lane >> 2;
        int px1 = px0 + g, px2 = px1 + 8;
        float a1v = alps[px1], a2v = alps[px2];
        int ob1 = tile_base + (rbase + wid)*W_ + g;
        int ob2 = ob1 + 8;
        #pragma unroll
        for (int p = 0; p < 4; ++p) {
            #pragma unroll
            for (int s = 0; s < 2; ++s) {
                int jj = 2*p + s;
                int c  = 16*p + 8*s + t2;
                float d0 = acc2[jj][0] + b2s[c];
                float d1 = acc2[jj][1] + b2s[c+1];
                float d2 = acc2[jj][2] + b2s[c];
                float d3 = acc2[jj][3] + b2s[c+1];
                u32 xh1 = *(const u32*)(smc + XHI_ + px1*144 + c*2);
                u32 xl1 = *(const u32*)(smc + XLO_ + px1*144 + c*2);
                u32 xh2 = *(const u32*)(smc + XHI_ + px2*144 + c*2);
                u32 xl2 = *(const u32*)(smc + XLO_ + px2*144 + c*2);
                int o0 = ob1 + c*HW_;
                int o2 = ob2 + c*HW_;
                det[o0]       = d0;
                det[o0 + HW_] = d1;
                det[o2]       = d2;
                det[o2 + HW_] = d3;
                heavy[o0]       = fmaf(a1v, d0, bf_lo(xh1) + bf_lo(xl1));
                heavy[o0 + HW_] = fmaf(a1v, d1, bf_hi(xh1) + bf_hi(xl1));
                heavy[o2]       = fmaf(a2v, d2, bf_lo(xh2) + bf_lo(xl2));
                heavy[o2 + HW_] = fmaf(a2v, d3, bf_hi(xh2) + bf_hi(xl2));
            }
        }
    }
}

// ---------------- launcher ----------------
extern "C" void kernel_launch(void* const* d_in, const int* in_sizes, int n_in,
                              void* d_out, int out_size) {
    const float* x  = (const float*)d_in[0];
    const float* u  = (const float*)d_in[1];
    const float* W1 = (const float*)d_in[2];
    const float* b1 = (const float*)d_in[3];
    const float* W2 = (const float*)d_in[4];
    const float* b2 = (const float*)d_in[5];
    const float* Wa = (const float*)d_in[6];
    const float* ba = (const float*)d_in[7];
    float* out = (float*)d_out;

    cudaFuncSetAttribute(main_kernel,
                         cudaFuncAttributeMaxDynamicSharedMemorySize, SMEM_BYTES);

    prep_kernel<<<5, 1024>>>(u, W1, W2, out);
    main_kernel<<<2*B_*K_, 256, SMEM_BYTES>>>(x, b1, b2, Wa, ba, out);
}

// round 15
// speedup vs baseline: 1.2416x; 1.2416x over previous
#include <cuda_runtime.h>

// ---------------- problem constants ----------------
#define B_    2
#define C_    64
#define H_    512
#define W_    512
#define T_    16
#define K_    1024
#define KMAX_ 256
#define HID_  128
#define HW_   (H_*W_)
#define CHW_  (C_*HW_)

// output layout (flatten-concat, all f32)
#define HEAVY_OFF  0
#define DET_OFF    33554432
#define ALPHA_OFF  67108864
#define P_OFF      67633152
#define G_OFF      67635200
#define COST_OFF   67637248
#define BL_OFF     67637249

typedef unsigned int u32;
typedef unsigned long long u64;

// ---------------- helpers ----------------
__device__ __forceinline__ u32 smem_u32(const void* p) {
    u32 a;
    asm("{ .reg .u64 t; cvta.to.shared.u64 t, %1; cvt.u32.u64 %0, t; }"
        : "=r"(a) : "l"(p));
    return a;
}
__device__ __forceinline__ float fast_sigmoid(float v) {
    return __fdividef(1.f, 1.f + __expf(-v));
}
__device__ __forceinline__ float gelu_tanh(float v) {
    float z  = 0.7978845608028654f * fmaf(0.044715f * v, v * v, v);
    float th; asm("tanh.approx.f32 %0, %1;" : "=f"(th) : "f"(z));
    return 0.5f * v * (1.f + th);
}
// split (v0,v1) into packed bf16x2 hi and lo (v ~= hi + lo)
__device__ __forceinline__ void split2(float v0, float v1, u32& hi, u32& lo) {
    u32 h; asm("cvt.rn.bf16x2.f32 %0, %1, %2;" : "=r"(h) : "f"(v1), "f"(v0));
    float f0 = __uint_as_float(h << 16);
    float f1 = __uint_as_float(h & 0xFFFF0000u);
    u32 l; asm("cvt.rn.bf16x2.f32 %0, %1, %2;" : "=r"(l) : "f"(v1 - f1), "f"(v0 - f0));
    hi = h; lo = l;
}
__device__ __forceinline__ float bf_lo(u32 v) { return __uint_as_float(v << 16); }
__device__ __forceinline__ float bf_hi(u32 v) { return __uint_as_float(v & 0xFFFF0000u); }

__device__ __forceinline__ void ldsm4(u32* r, u32 a) {
    asm volatile("ldmatrix.sync.aligned.m8n8.x4.shared.b16 {%0,%1,%2,%3}, [%4];"
        : "=r"(r[0]), "=r"(r[1]), "=r"(r[2]), "=r"(r[3]) : "r"(a));
}
__device__ __forceinline__ void ldsm4t(u32* r, u32 a) {
    asm volatile("ldmatrix.sync.aligned.m8n8.x4.trans.shared.b16 {%0,%1,%2,%3}, [%4];"
        : "=r"(r[0]), "=r"(r[1]), "=r"(r[2]), "=r"(r[3]) : "r"(a));
}
__device__ __forceinline__ void mma16816(float* d, const u32* a, u32 b0, u32 b1) {
    asm volatile(
        "mma.sync.aligned.m16n8k16.row.col.f32.bf16.bf16.f32 "
        "{%0,%1,%2,%3}, {%4,%5,%6,%7}, {%8,%9}, {%0,%1,%2,%3};"
        : "+f"(d[0]), "+f"(d[1]), "+f"(d[2]), "+f"(d[3])
        : "r"(a[0]), "r"(a[1]), "r"(a[2]), "r"(a[3]), "r"(b0), "r"(b1));
}

// ---------------- SMEM layout (byte offsets) ----------------
#define XHI_   0        // [128px][64c] bf16, pitch 144   -> 18432
#define XLO_   18432
#define W1HI_  36864    // [64c][128d] bf16, pitch 272    -> 17408
#define W1LO_  54272
#define W2HI_  71680    // [128d][64c] bf16, pitch 144    -> 18432
#define W2LO_  90112
#define ALPS_  108544   // 128 f32
#define B1S_   109056   // 128 f32
#define B2S_   109568   // 64 f32
#define WAS_   109824   // 64 f32
#define BAS_   110080   // 1 f32
#define REDS_  110084   // 8 x 4B reduction scratch
#define SELF_  110116   // selection flag
#define SMEM_BYTES 110128

// ---------------- single fused kernel ----------------
// grid = 2*B*K half-tile blocks (128 px), 256 threads, 2 CTAs/SM.
// Block 0 additionally computes gates/cost. Every block decides its own
// tile selection in-block (rank-count top-KMAX over the sample's 1024 u).
__global__ void __launch_bounds__(256, 2)
main_kernel(const float* __restrict__ x,  const float* __restrict__ u,
            const float* __restrict__ W1, const float* __restrict__ W2,
            const float* __restrict__ b1, const float* __restrict__ b2,
            const float* __restrict__ Wa, const float* __restrict__ ba,
            float* __restrict__ out) {
    extern __shared__ char smc[];
    const int blk  = blockIdx.x;
    const int tile = blk >> 1;
    const int half = blk & 1;
    const int b    = tile >> 10;
    const int k    = tile & (K_-1);
    const int gh   = k >> 5, gw = k & 31;
    const int t    = threadIdx.x;
    const int wid  = t >> 5, lane = t & 31;

    float* heavy = out + HEAVY_OFF;
    float* det   = out + DET_OFF;
    float* alp   = out + ALPHA_OFF;

    // ---- block 0: gate probabilities + expected cost + budget loss ----
    if (blk == 0) {
        float partial = 0.f;
        #pragma unroll
        for (int e = t; e < B_*K_; e += 256) {
            float uv = u[e];
            float p  = fast_sigmoid(uv);
            float hard = (uv >= 0.f) ? 1.f : 0.f;
            float gate = (hard + p) - p;
            out[P_OFF + e] = p;
            out[G_OFF + e] = gate;
            partial += fmaf(p, 0.9f, 0.1f);
        }
        #pragma unroll
        for (int s = 16; s > 0; s >>= 1)
            partial += __shfl_xor_sync(0xFFFFFFFFu, partial, s);
        if (lane == 0) ((float*)(smc + REDS_))[wid] = partial;
        __syncthreads();
        if (t == 0) {
            float cost = 0.f;
            #pragma unroll
            for (int w = 0; w < 8; ++w) cost += ((float*)(smc + REDS_))[w];
            out[COST_OFF] = cost;
            float bl = cost - 1024.f;      // BUDGET_TOTAL*B
            out[BL_OFF] = bl > 0.f ? bl : 0.f;
        }
        __syncthreads();
    }

    // ---- in-block tile selection: rank-count top-KMAX ----
    {
        const float* ub = u + b*K_;
        float ue = __ldg(ub + k);
        float4 uq = ((const float4*)ub)[t];
        int j0 = 4*t;
        int cnt = 0;
        if (ue >= 0.f) {
            cnt  = (uq.x >= 0.f && (uq.x > ue || (uq.x == ue && j0     < k)));
            cnt += (uq.y >= 0.f && (uq.y > ue || (uq.y == ue && j0 + 1 < k)));
            cnt += (uq.z >= 0.f && (uq.z > ue || (uq.z == ue && j0 + 2 < k)));
            cnt += (uq.w >= 0.f && (uq.w > ue || (uq.w == ue && j0 + 3 < k)));
        }
        #pragma unroll
        for (int s = 16; s > 0; s >>= 1)
            cnt += __shfl_xor_sync(0xFFFFFFFFu, cnt, s);
        if (lane == 0) ((int*)(smc + REDS_))[wid] = cnt;
        __syncthreads();
        if (t == 0) {
            int tot = 0;
            #pragma unroll
            for (int w = 0; w < 8; ++w) tot += ((int*)(smc + REDS_))[w];
            *(int*)(smc + SELF_) = (ue >= 0.f && tot < KMAX_) ? 1 : 0;
        }
        __syncthreads();
    }

    const int tile_base = b*CHW_ + (gh*T_)*W_ + gw*T_;
    const int rbase = half*8;

    if (!*(const int*)(smc + SELF_)) {
        // ---- cheap path: heavy = x, detail = 0, alpha = 0 ----
        #pragma unroll 8
        for (int i = t; i < 2048; i += 256) {
            int c = i >> 5; int l = i & 31;
            int off = tile_base + c*HW_ + (rbase + (l >> 2))*W_ + (l & 3)*4;
            float4 v = *(const float4*)(x + off);
            *(float4*)(heavy + off) = v;
            *(float4*)(det   + off) = make_float4(0.f,0.f,0.f,0.f);
        }
        if (t < 32) {
            int aoff = b*HW_ + (gh*T_ + rbase + (t >> 2))*W_ + gw*T_ + (t & 3)*4;
            *(float4*)(alp + aoff) = make_float4(0.f,0.f,0.f,0.f);
        }
        return;
    }

    // ================= staging =================
    #pragma unroll
    for (int it = 0; it < 4; ++it) {
        int s  = it*256 + t;
        int px = s & 127;
        int c8 = s >> 7;
        int gb = tile_base + (rbase + (px >> 4))*W_ + (px & 15);
        float v[8];
        #pragma unroll
        for (int m = 0; m < 8; ++m) v[m] = x[gb + (c8*8 + m)*HW_];
        u32 h[4], l[4];
        split2(v[0], v[1], h[0], l[0]);
        split2(v[2], v[3], h[1], l[1]);
        split2(v[4], v[5], h[2], l[2]);
        split2(v[6], v[7], h[3], l[3]);
        *(uint4*)(smc + XHI_ + px*144 + c8*16) = make_uint4(h[0],h[1],h[2],h[3]);
        *(uint4*)(smc + XLO_ + px*144 + c8*16) = make_uint4(l[0],l[1],l[2],l[3]);
    }
    // W1: [c=64][d=128] f32 -> bf16 hi/lo, [c][d-pair] pitch 272B
    #pragma unroll
    for (int s = t; s < 2048; s += 256) {
        int c = s >> 5, q = s & 31;
        float4 v = ((const float4*)W1)[s];
        u32 h0,l0,h1,l1;
        split2(v.x, v.y, h0, l0);
        split2(v.z, v.w, h1, l1);
        *(u64*)(smc + W1HI_ + c*272 + q*8) = (u64)h0 | ((u64)h1 << 32);
        *(u64*)(smc + W1LO_ + c*272 + q*8) = (u64)l0 | ((u64)l1 << 32);
    }
    // W2: [d=128][c=64] f32 -> bf16 hi/lo, [d][c-pair] pitch 144B
    #pragma unroll
    for (int s = t; s < 2048; s += 256) {
        int d = s >> 4, q = s & 15;
        float4 v = ((const float4*)W2)[s];
        u32 h0,l0,h1,l1;
        split2(v.x, v.y, h0, l0);
        split2(v.z, v.w, h1, l1);
        *(u64*)(smc + W2HI_ + d*144 + q*8) = (u64)h0 | ((u64)h1 << 32);
        *(u64*)(smc + W2LO_ + d*144 + q*8) = (u64)l0 | ((u64)l1 << 32);
    }
    if (t < HID_) *(float*)(smc + B1S_ + t*4) = b1[t];
    if (t < C_)  { *(float*)(smc + B2S_ + t*4) = b2[t];
                   *(float*)(smc + WAS_ + t*4) = Wa[t]; }
    if (t == 0)   *(float*)(smc + BAS_) = ba[0];
    __syncthreads();

    const u32 sb   = smem_u32(smc);
    const int px0  = 16*wid;
    const float* b1s = (const float*)(smc + B1S_);
    const float* b2s = (const float*)(smc + B2S_);
    float* alps = (float*)(smc + ALPS_);

    // ---- alpha: lanes 0-15 each handle one of this warp's 16 px ----
    if (lane < 16) {
        int px = px0 + lane;
        float acc = *(const float*)(smc + BAS_);
        const float* was = (const float*)(smc + WAS_);
        #pragma unroll 8
        for (int c2 = 0; c2 < 32; ++c2) {
            u32 hv = *(const u32*)(smc + XHI_ + px*144 + c2*4);
            u32 lv = *(const u32*)(smc + XLO_ + px*144 + c2*4);
            acc = fmaf(bf_lo(hv) + bf_lo(lv), was[2*c2],   acc);
            acc = fmaf(bf_hi(hv) + bf_hi(lv), was[2*c2+1], acc);
        }
        float av = fast_sigmoid(acc);
        alps[px] = av;
        int aoff = b*HW_ + (gh*T_ + rbase + (px >> 4))*W_ + gw*T_ + (px & 15);
        alp[aoff] = av;
    }
    __syncwarp();

    // ---- fragment base addresses ----
    const u32 lrow16 = (u32)(lane & 15);
    const u32 lhalf  = (u32)(lane >> 4);
    const u32 xA  = sb + XHI_  + (px0 + lrow16)*144 + lhalf*16;
    const u32 xAl = sb + XLO_  + (px0 + lrow16)*144 + lhalf*16;
    const u32 w1A = sb + W1HI_ + lrow16*272 + lhalf*16;
    const u32 w1Al= sb + W1LO_ + lrow16*272 + lhalf*16;
    const u32 w2A = sb + W2HI_ + lrow16*144 + lhalf*16;
    const u32 w2Al= sb + W2LO_ + lrow16*144 + lhalf*16;

    u32 xh[4][4], xl[4][4];
    #pragma unroll
    for (int kt = 0; kt < 4; ++kt) {
        ldsm4(xh[kt], xA  + kt*32);
        ldsm4(xl[kt], xAl + kt*32);
    }

    // ---- GEMM1: D1[16px][128d] ----
    float acc[16][4];
    #pragma unroll
    for (int j = 0; j < 16; ++j)
        #pragma unroll
        for (int q = 0; q < 4; ++q) acc[j][q] = 0.f;

    #pragma unroll
    for (int nt = 0; nt < 8; ++nt) {
        #pragma unroll
        for (int kt = 0; kt < 4; ++kt) {
            u32 bh[4], bl_[4];
            ldsm4t(bh,  w1A  + kt*16*272 + nt*32);
            ldsm4t(bl_, w1Al + kt*16*272 + nt*32);
            mma16816(acc[2*nt],   xh[kt], bh[0],  bh[1]);
            mma16816(acc[2*nt],   xh[kt], bl_[0], bl_[1]);
            mma16816(acc[2*nt],   xl[kt], bh[0],  bh[1]);
            mma16816(acc[2*nt+1], xh[kt], bh[2],  bh[3]);
            mma16816(acc[2*nt+1], xh[kt], bl_[2], bl_[3]);
            mma16816(acc[2*nt+1], xl[kt], bh[2],  bh[3]);
        }
    }

    // ---- D1 -> gelu -> H A-fragments in registers ----
    const int t2 = (lane & 3)*2;
    u32 ah[8][4], al[8][4];
    #pragma unroll
    for (int kt = 0; kt < 8; ++kt) {
        int dbase = 16*kt + t2;
        float bA0 = b1s[dbase],     bA1 = b1s[dbase+1];
        float bB0 = b1s[dbase+8],   bB1 = b1s[dbase+9];
        float h00 = gelu_tanh(acc[2*kt][0]   + bA0);
        float h01 = gelu_tanh(acc[2*kt][1]   + bA1);
        float h10 = gelu_tanh(acc[2*kt][2]   + bA0);
        float h11 = gelu_tanh(acc[2*kt][3]   + bA1);
        float h20 = gelu_tanh(acc[2*kt+1][0] + bB0);
        float h21 = gelu_tanh(acc[2*kt+1][1] + bB1);
        float h30 = gelu_tanh(acc[2*kt+1][2] + bB0);
        float h31 = gelu_tanh(acc[2*kt+1][3] + bB1);
        split2(h00, h01, ah[kt][0], al[kt][0]);
        split2(h10, h11, ah[kt][1], al[kt][1]);
        split2(h20, h21, ah[kt][2], al[kt][2]);
        split2(h30, h31, ah[kt][3], al[kt][3]);
    }

    // ---- GEMM2: D2[16px][64c] ----
    float acc2[8][4];
    #pragma unroll
    for (int j = 0; j < 8; ++j)
        #pragma unroll
        for (int q = 0; q < 4; ++q) acc2[j][q] = 0.f;

    #pragma unroll
    for (int nt = 0; nt < 4; ++nt) {
        #pragma unroll
        for (int kt = 0; kt < 8; ++kt) {
            u32 bh[4], bl_[4];
            ldsm4t(bh,  w2A  + kt*16*144 + nt*32);
            ldsm4t(bl_, w2Al + kt*16*144 + nt*32);
            mma16816(acc2[2*nt],   ah[kt], bh[0],  bh[1]);
            mma16816(acc2[2*nt],   ah[kt], bl_[0], bl_[1]);
            mma16816(acc2[2*nt],   al[kt], bh[0],  bh[1]);
            mma16816(acc2[2*nt+1], ah[kt], bh[2],  bh[3]);
            mma16816(acc2[2*nt+1], ah[kt], bl_[2], bl_[3]);
            mma16816(acc2[2*nt+1], al[kt], bh[2],  bh[3]);
        }
    }

    // ---- epilogue: det = D2 + b2 ; heavy = x + alpha*det ----
    {
        int g   = lane >> 2;
        int px1 = px0 + g, px2 = px1 + 8;
        float a1v = alps[px1], a2v = alps[px2];
        int ob1 = tile_base + (rbase + wid)*W_ + g;
        int ob2 = ob1 + 8;
        #pragma unroll
        for (int p = 0; p < 4; ++p) {
            #pragma unroll
            for (int s = 0; s < 2; ++s) {
                int jj = 2*p + s;
                int c  = 16*p + 8*s + t2;
                float d0 = acc2[jj][0] + b2s[c];
                float d1 = acc2[jj][1] + b2s[c+1];
                float d2 = acc2[jj][2] + b2s[c];
                float d3 = acc2[jj][3] + b2s[c+1];
                u32 xh1 = *(const u32*)(smc + XHI_ + px1*144 + c*2);
                u32 xl1 = *(const u32*)(smc + XLO_ + px1*144 + c*2);
                u32 xh2 = *(const u32*)(smc + XHI_ + px2*144 + c*2);
                u32 xl2 = *(const u32*)(smc + XLO_ + px2*144 + c*2);
                int o0 = ob1 + c*HW_;
                int o2 = ob2 + c*HW_;
                det[o0]       = d0;
                det[o0 + HW_] = d1;
                det[o2]       = d2;
                det[o2 + HW_] = d3;
                heavy[o0]       = fmaf(a1v, d0, bf_lo(xh1) + bf_lo(xl1));
                heavy[o0 + HW_] = fmaf(a1v, d1, bf_hi(xh1) + bf_hi(xl1));
                heavy[o2]       = fmaf(a2v, d2, bf_lo(xh2) + bf_lo(xl2));
                heavy[o2 + HW_] = fmaf(a2v, d3, bf_hi(xh2) + bf_hi(xl2));
            }
        }
    }
}

// ---------------- launcher ----------------
extern "C" void kernel_launch(void* const* d_in, const int* in_sizes, int n_in,
                              void* d_out, int out_size) {
    const float* x  = (const float*)d_in[0];
    const float* u  = (const float*)d_in[1];
    const float* W1 = (const float*)d_in[2];
    const float* b1 = (const float*)d_in[3];
    const float* W2 = (const float*)d_in[4];
    const float* b2 = (const float*)d_in[5];
    const float* Wa = (const float*)d_in[6];
    const float* ba = (const float*)d_in[7];
    float* out = (float*)d_out;

    cudaFuncSetAttribute(main_kernel,
                         cudaFuncAttributeMaxDynamicSharedMemorySize, SMEM_BYTES);

    main_kernel<<<2*B_*K_, 256, SMEM_BYTES>>>(x, u, W1, W2, b1, b2, Wa, ba, out);
}

// round 16
// speedup vs baseline: 1.2582x; 1.0134x over previous
#include <cuda_runtime.h>

// ---------------- problem constants ----------------
#define B_    2
#define C_    64
#define H_    512
#define W_    512
#define T_    16
#define K_    1024
#define KMAX_ 256
#define HID_  128
#define HW_   (H_*W_)
#define CHW_  (C_*HW_)

// output layout (flatten-concat, all f32)
#define HEAVY_OFF  0
#define DET_OFF    33554432
#define ALPHA_OFF  67108864
#define P_OFF      67633152
#define G_OFF      67635200
#define COST_OFF   67637248
#define BL_OFF     67637249

typedef unsigned int u32;
typedef unsigned long long u64;

// ---------------- helpers ----------------
__device__ __forceinline__ u32 smem_u32(const void* p) {
    u32 a;
    asm("{ .reg .u64 t; cvta.to.shared.u64 t, %1; cvt.u32.u64 %0, t; }"
        : "=r"(a) : "l"(p));
    return a;
}
__device__ __forceinline__ float fast_sigmoid(float v) {
    return __fdividef(1.f, 1.f + __expf(-v));
}
__device__ __forceinline__ float gelu_tanh(float v) {
    float z  = 0.7978845608028654f * fmaf(0.044715f * v, v * v, v);
    float th; asm("tanh.approx.f32 %0, %1;" : "=f"(th) : "f"(z));
    return 0.5f * v * (1.f + th);
}
// split (v0,v1) into packed bf16x2 hi and lo (v ~= hi + lo)
__device__ __forceinline__ void split2(float v0, float v1, u32& hi, u32& lo) {
    u32 h; asm("cvt.rn.bf16x2.f32 %0, %1, %2;" : "=r"(h) : "f"(v1), "f"(v0));
    float f0 = __uint_as_float(h << 16);
    float f1 = __uint_as_float(h & 0xFFFF0000u);
    u32 l; asm("cvt.rn.bf16x2.f32 %0, %1, %2;" : "=r"(l) : "f"(v1 - f1), "f"(v0 - f0));
    hi = h; lo = l;
}
__device__ __forceinline__ float bf_lo(u32 v) { return __uint_as_float(v << 16); }
__device__ __forceinline__ float bf_hi(u32 v) { return __uint_as_float(v & 0xFFFF0000u); }

__device__ __forceinline__ void ldsm4(u32* r, u32 a) {
    asm volatile("ldmatrix.sync.aligned.m8n8.x4.shared.b16 {%0,%1,%2,%3}, [%4];"
        : "=r"(r[0]), "=r"(r[1]), "=r"(r[2]), "=r"(r[3]) : "r"(a));
}
__device__ __forceinline__ void ldsm4t(u32* r, u32 a) {
    asm volatile("ldmatrix.sync.aligned.m8n8.x4.trans.shared.b16 {%0,%1,%2,%3}, [%4];"
        : "=r"(r[0]), "=r"(r[1]), "=r"(r[2]), "=r"(r[3]) : "r"(a));
}
__device__ __forceinline__ void mma16816(float* d, const u32* a, u32 b0, u32 b1) {
    asm volatile(
        "mma.sync.aligned.m16n8k16.row.col.f32.bf16.bf16.f32 "
        "{%0,%1,%2,%3}, {%4,%5,%6,%7}, {%8,%9}, {%0,%1,%2,%3};"
        : "+f"(d[0]), "+f"(d[1]), "+f"(d[2]), "+f"(d[3])
        : "r"(a[0]), "r"(a[1]), "r"(a[2]), "r"(a[3]), "r"(b0), "r"(b1));
}

// ---------------- SMEM layout (byte offsets) ----------------
#define XHI_   0        // [128px][64c] bf16, pitch 144   -> 18432
#define XLO_   18432
#define W1HI_  36864    // [64c][128d] bf16, pitch 272    -> 17408
#define W1LO_  54272
#define W2HI_  71680    // [128d][64c] bf16, pitch 144    -> 18432
#define W2LO_  90112
#define ALPS_  108544   // 128 f32
#define B1S_   109056   // 128 f32
#define B2S_   109568   // 64 f32
#define WAS_   109824   // 64 f32
#define BAS_   110080   // 1 f32
#define REDS_  110084   // 8 x 4B reduction scratch
#define SELF_  110116   // selection flag
#define SMEM_BYTES 110128

// ---------------- single fused kernel ----------------
// grid = 2*B*K half-tile blocks (128 px), 256 threads, 2 CTAs/SM.
// Block 0 additionally computes gates/cost. Every block decides its own
// tile selection in-block. GEMM loops are kt-outer / nt-inner so successive
// HMMAs target different accumulators (16-way / 8-way chain ILP).
__global__ void __launch_bounds__(256, 2)
main_kernel(const float* __restrict__ x,  const float* __restrict__ u,
            const float* __restrict__ W1, const float* __restrict__ W2,
            const float* __restrict__ b1, const float* __restrict__ b2,
            const float* __restrict__ Wa, const float* __restrict__ ba,
            float* __restrict__ out) {
    extern __shared__ char smc[];
    const int blk  = blockIdx.x;
    const int tile = blk >> 1;
    const int half = blk & 1;
    const int b    = tile >> 10;
    const int k    = tile & (K_-1);
    const int gh   = k >> 5, gw = k & 31;
    const int t    = threadIdx.x;
    const int wid  = t >> 5, lane = t & 31;

    float* heavy = out + HEAVY_OFF;
    float* det   = out + DET_OFF;
    float* alp   = out + ALPHA_OFF;

    // ---- block 0: gate probabilities + expected cost + budget loss ----
    if (blk == 0) {
        float partial = 0.f;
        #pragma unroll
        for (int e = t; e < B_*K_; e += 256) {
            float uv = u[e];
            float p  = fast_sigmoid(uv);
            float hard = (uv >= 0.f) ? 1.f : 0.f;
            float gate = (hard + p) - p;
            out[P_OFF + e] = p;
            out[G_OFF + e] = gate;
            partial += fmaf(p, 0.9f, 0.1f);
        }
        #pragma unroll
        for (int s = 16; s > 0; s >>= 1)
            partial += __shfl_xor_sync(0xFFFFFFFFu, partial, s);
        if (lane == 0) ((float*)(smc + REDS_))[wid] = partial;
        __syncthreads();
        if (t == 0) {
            float cost = 0.f;
            #pragma unroll
            for (int w = 0; w < 8; ++w) cost += ((float*)(smc + REDS_))[w];
            out[COST_OFF] = cost;
            float bl = cost - 1024.f;      // BUDGET_TOTAL*B
            out[BL_OFF] = bl > 0.f ? bl : 0.f;
        }
        __syncthreads();
    }

    // ---- in-block tile selection: rank-count top-KMAX ----
    {
        const float* ub = u + b*K_;
        float ue = __ldg(ub + k);
        float4 uq = ((const float4*)ub)[t];
        int j0 = 4*t;
        int cnt = 0;
        if (ue >= 0.f) {
            cnt  = (uq.x >= 0.f && (uq.x > ue || (uq.x == ue && j0     < k)));
            cnt += (uq.y >= 0.f && (uq.y > ue || (uq.y == ue && j0 + 1 < k)));
            cnt += (uq.z >= 0.f && (uq.z > ue || (uq.z == ue && j0 + 2 < k)));
            cnt += (uq.w >= 0.f && (uq.w > ue || (uq.w == ue && j0 + 3 < k)));
        }
        #pragma unroll
        for (int s = 16; s > 0; s >>= 1)
            cnt += __shfl_xor_sync(0xFFFFFFFFu, cnt, s);
        if (lane == 0) ((int*)(smc + REDS_))[wid] = cnt;
        __syncthreads();
        if (t == 0) {
            int tot = 0;
            #pragma unroll
            for (int w = 0; w < 8; ++w) tot += ((int*)(smc + REDS_))[w];
            *(int*)(smc + SELF_) = (ue >= 0.f && tot < KMAX_) ? 1 : 0;
        }
        __syncthreads();
    }

    const int tile_base = b*CHW_ + (gh*T_)*W_ + gw*T_;
    const int rbase = half*8;

    if (!*(const int*)(smc + SELF_)) {
        // ---- cheap path: heavy = x, detail = 0, alpha = 0 ----
        #pragma unroll 8
        for (int i = t; i < 2048; i += 256) {
            int c = i >> 5; int l = i & 31;
            int off = tile_base + c*HW_ + (rbase + (l >> 2))*W_ + (l & 3)*4;
            float4 v = *(const float4*)(x + off);
            *(float4*)(heavy + off) = v;
            *(float4*)(det   + off) = make_float4(0.f,0.f,0.f,0.f);
        }
        if (t < 32) {
            int aoff = b*HW_ + (gh*T_ + rbase + (t >> 2))*W_ + gw*T_ + (t & 3)*4;
            *(float4*)(alp + aoff) = make_float4(0.f,0.f,0.f,0.f);
        }
        return;
    }

    // ================= staging =================
    #pragma unroll
    for (int it = 0; it < 4; ++it) {
        int s  = it*256 + t;
        int px = s & 127;
        int c8 = s >> 7;
        int gb = tile_base + (rbase + (px >> 4))*W_ + (px & 15);
        float v[8];
        #pragma unroll
        for (int m = 0; m < 8; ++m) v[m] = x[gb + (c8*8 + m)*HW_];
        u32 h[4], l[4];
        split2(v[0], v[1], h[0], l[0]);
        split2(v[2], v[3], h[1], l[1]);
        split2(v[4], v[5], h[2], l[2]);
        split2(v[6], v[7], h[3], l[3]);
        *(uint4*)(smc + XHI_ + px*144 + c8*16) = make_uint4(h[0],h[1],h[2],h[3]);
        *(uint4*)(smc + XLO_ + px*144 + c8*16) = make_uint4(l[0],l[1],l[2],l[3]);
    }
    // W1: [c=64][d=128] f32 -> bf16 hi/lo, [c][d-pair] pitch 272B
    #pragma unroll
    for (int s = t; s < 2048; s += 256) {
        int c = s >> 5, q = s & 31;
        float4 v = ((const float4*)W1)[s];
        u32 h0,l0,h1,l1;
        split2(v.x, v.y, h0, l0);
        split2(v.z, v.w, h1, l1);
        *(u64*)(smc + W1HI_ + c*272 + q*8) = (u64)h0 | ((u64)h1 << 32);
        *(u64*)(smc + W1LO_ + c*272 + q*8) = (u64)l0 | ((u64)l1 << 32);
    }
    // W2: [d=128][c=64] f32 -> bf16 hi/lo, [d][c-pair] pitch 144B
    #pragma unroll
    for (int s = t; s < 2048; s += 256) {
        int d = s >> 4, q = s & 15;
        float4 v = ((const float4*)W2)[s];
        u32 h0,l0,h1,l1;
        split2(v.x, v.y, h0, l0);
        split2(v.z, v.w, h1, l1);
        *(u64*)(smc + W2HI_ + d*144 + q*8) = (u64)h0 | ((u64)h1 << 32);
        *(u64*)(smc + W2LO_ + d*144 + q*8) = (u64)l0 | ((u64)l1 << 32);
    }
    if (t < HID_) *(float*)(smc + B1S_ + t*4) = b1[t];
    if (t < C_)  { *(float*)(smc + B2S_ + t*4) = b2[t];
                   *(float*)(smc + WAS_ + t*4) = Wa[t]; }
    if (t == 0)   *(float*)(smc + BAS_) = ba[0];
    __syncthreads();

    const u32 sb   = smem_u32(smc);
    const int px0  = 16*wid;
    const float* b1s = (const float*)(smc + B1S_);
    const float* b2s = (const float*)(smc + B2S_);
    float* alps = (float*)(smc + ALPS_);

    // ---- alpha: lanes 0-15 each handle one of this warp's 16 px ----
    if (lane < 16) {
        int px = px0 + lane;
        float acc = *(const float*)(smc + BAS_);
        const float* was = (const float*)(smc + WAS_);
        #pragma unroll 8
        for (int c2 = 0; c2 < 32; ++c2) {
            u32 hv = *(const u32*)(smc + XHI_ + px*144 + c2*4);
            u32 lv = *(const u32*)(smc + XLO_ + px*144 + c2*4);
            acc = fmaf(bf_lo(hv) + bf_lo(lv), was[2*c2],   acc);
            acc = fmaf(bf_hi(hv) + bf_hi(lv), was[2*c2+1], acc);
        }
        float av = fast_sigmoid(acc);
        alps[px] = av;
        int aoff = b*HW_ + (gh*T_ + rbase + (px >> 4))*W_ + gw*T_ + (px & 15);
        alp[aoff] = av;
    }
    __syncwarp();

    // ---- fragment base addresses ----
    const u32 lrow16 = (u32)(lane & 15);
    const u32 lhalf  = (u32)(lane >> 4);
    const u32 xA  = sb + XHI_  + (px0 + lrow16)*144 + lhalf*16;
    const u32 xAl = sb + XLO_  + (px0 + lrow16)*144 + lhalf*16;
    const u32 w1A = sb + W1HI_ + lrow16*272 + lhalf*16;
    const u32 w1Al= sb + W1LO_ + lrow16*272 + lhalf*16;
    const u32 w2A = sb + W2HI_ + lrow16*144 + lhalf*16;
    const u32 w2Al= sb + W2LO_ + lrow16*144 + lhalf*16;

    u32 xh[4][4], xl[4][4];
    #pragma unroll
    for (int kt = 0; kt < 4; ++kt) {
        ldsm4(xh[kt], xA  + kt*32);
        ldsm4(xl[kt], xAl + kt*32);
    }

    // ---- GEMM1: D1[16px][128d] — kt OUTER / nt INNER (16 indep chains) ----
    float acc[16][4];
    #pragma unroll
    for (int j = 0; j < 16; ++j)
        #pragma unroll
        for (int q = 0; q < 4; ++q) acc[j][q] = 0.f;

    #pragma unroll
    for (int kt = 0; kt < 4; ++kt) {
        #pragma unroll
        for (int nt = 0; nt < 8; ++nt) {
            u32 bh[4], bl_[4];
            ldsm4t(bh,  w1A  + kt*16*272 + nt*32);
            ldsm4t(bl_, w1Al + kt*16*272 + nt*32);
            mma16816(acc[2*nt],   xh[kt], bh[0],  bh[1]);
            mma16816(acc[2*nt+1], xh[kt], bh[2],  bh[3]);
            mma16816(acc[2*nt],   xh[kt], bl_[0], bl_[1]);
            mma16816(acc[2*nt+1], xh[kt], bl_[2], bl_[3]);
            mma16816(acc[2*nt],   xl[kt], bh[0],  bh[1]);
            mma16816(acc[2*nt+1], xl[kt], bh[2],  bh[3]);
        }
    }

    // ---- D1 -> gelu -> H A-fragments in registers ----
    const int t2 = (lane & 3)*2;
    u32 ah[8][4], al[8][4];
    #pragma unroll
    for (int kt = 0; kt < 8; ++kt) {
        int dbase = 16*kt + t2;
        float bA0 = b1s[dbase],     bA1 = b1s[dbase+1];
        float bB0 = b1s[dbase+8],   bB1 = b1s[dbase+9];
        float h00 = gelu_tanh(acc[2*kt][0]   + bA0);
        float h01 = gelu_tanh(acc[2*kt][1]   + bA1);
        float h10 = gelu_tanh(acc[2*kt][2]   + bA0);
        float h11 = gelu_tanh(acc[2*kt][3]   + bA1);
        float h20 = gelu_tanh(acc[2*kt+1][0] + bB0);
        float h21 = gelu_tanh(acc[2*kt+1][1] + bB1);
        float h30 = gelu_tanh(acc[2*kt+1][2] + bB0);
        float h31 = gelu_tanh(acc[2*kt+1][3] + bB1);
        split2(h00, h01, ah[kt][0], al[kt][0]);
        split2(h10, h11, ah[kt][1], al[kt][1]);
        split2(h20, h21, ah[kt][2], al[kt][2]);
        split2(h30, h31, ah[kt][3], al[kt][3]);
    }

    // ---- GEMM2: D2[16px][64c] — kt OUTER / nt INNER (8 indep chains) ----
    float acc2[8][4];
    #pragma unroll
    for (int j = 0; j < 8; ++j)
        #pragma unroll
        for (int q = 0; q < 4; ++q) acc2[j][q] = 0.f;

    #pragma unroll
    for (int kt = 0; kt < 8; ++kt) {
        #pragma unroll
        for (int nt = 0; nt < 4; ++nt) {
            u32 bh[4], bl_[4];
            ldsm4t(bh,  w2A  + kt*16*144 + nt*32);
            ldsm4t(bl_, w2Al + kt*16*144 + nt*32);
            mma16816(acc2[2*nt],   ah[kt], bh[0],  bh[1]);
            mma16816(acc2[2*nt+1], ah[kt], bh[2],  bh[3]);
            mma16816(acc2[2*nt],   ah[kt], bl_[0], bl_[1]);
            mma16816(acc2[2*nt+1], ah[kt], bl_[2], bl_[3]);
            mma16816(acc2[2*nt],   al[kt], bh[0],  bh[1]);
            mma16816(acc2[2*nt+1], al[kt], bh[2],  bh[3]);
        }
    }

    // ---- epilogue: det = D2 + b2 ; heavy = x + alpha*det ----
    {
        int g   = lane >> 2;
        int px1 = px0 + g, px2 = px1 + 8;
        float a1v = alps[px1], a2v = alps[px2];
        int ob1 = tile_base + (rbase + wid)*W_ + g;
        int ob2 = ob1 + 8;
        #pragma unroll
        for (int p = 0; p < 4; ++p) {
            #pragma unroll
            for (int s = 0; s < 2; ++s) {
                int jj = 2*p + s;
                int c  = 16*p + 8*s + t2;
                float d0 = acc2[jj][0] + b2s[c];
                float d1 = acc2[jj][1] + b2s[c+1];
                float d2 = acc2[jj][2] + b2s[c];
                float d3 = acc2[jj][3] + b2s[c+1];
                u32 xh1 = *(const u32*)(smc + XHI_ + px1*144 + c*2);
                u32 xl1 = *(const u32*)(smc + XLO_ + px1*144 + c*2);
                u32 xh2 = *(const u32*)(smc + XHI_ + px2*144 + c*2);
                u32 xl2 = *(const u32*)(smc + XLO_ + px2*144 + c*2);
                int o0 = ob1 + c*HW_;
                int o2 = ob2 + c*HW_;
                det[o0]       = d0;
                det[o0 + HW_] = d1;
                det[o2]       = d2;
                det[o2 + HW_] = d3;
                heavy[o0]       = fmaf(a1v, d0, bf_lo(xh1) + bf_lo(xl1));
                heavy[o0 + HW_] = fmaf(a1v, d1, bf_hi(xh1) + bf_hi(xl1));
                heavy[o2]       = fmaf(a2v, d2, bf_lo(xh2) + bf_lo(xl2));
                heavy[o2 + HW_] = fmaf(a2v, d3, bf_hi(xh2) + bf_hi(xl2));
            }
        }
    }
}

// ---------------- launcher ----------------
extern "C" void kernel_launch(void* const* d_in, const int* in_sizes, int n_in,
                              void* d_out, int out_size) {
    const float* x  = (const float*)d_in[0];
    const float* u  = (const float*)d_in[1];
    const float* W1 = (const float*)d_in[2];
    const float* b1 = (const float*)d_in[3];
    const float* W2 = (const float*)d_in[4];
    const float* b2 = (const float*)d_in[5];
    const float* Wa = (const float*)d_in[6];
    const float* ba = (const float*)d_in[7];
    float* out = (float*)d_out;

    cudaFuncSetAttribute(main_kernel,
                         cudaFuncAttributeMaxDynamicSharedMemorySize, SMEM_BYTES);

    main_kernel<<<2*B_*K_, 256, SMEM_BYTES>>>(x, u, W1, W2, b1, b2, Wa, ba, out);
}